// round 1
// baseline (speedup 1.0000x reference)
#include <cuda_runtime.h>
#include <math.h>

#define BB   2
#define DD   2048
#define HH   16
#define DHD  128
#define TT   1280
#define LL   2048
#define LIP  512
#define MM   2560      // LL + LIP
#define TWOD 4096

// ------------------------- device scratch -------------------------
__device__ float g_emb[BB * TWOD];                        // shift|scale per batch
__device__ float g_ipn[BB * LIP * DD];                    // adaLN'd ip hidden states
__device__ float g_ipk[BB * LIP * DD];                    // ip_key  (pre-RMS)
__device__ float g_ipv[BB * LIP * DD];                    // ip_value
__device__ float g_q[(size_t)BB * HH * LL * DHD];         // rms(q) * 1/sqrt(d), (b,h,l,dh)
__device__ float g_k[(size_t)BB * HH * MM * DHD];         // [rms(k); rms(kip)]  (b,h,m,dh)
__device__ float g_v[(size_t)BB * HH * MM * DHD];         // [v; vip]

// ------------------------- kernel 1: emb = silu(t) @ W_ada^T + b -------------------------
__global__ void k_emb(const float* __restrict__ t_emb, const float* __restrict__ W,
                      const float* __restrict__ bias) {
    int gw   = (blockIdx.x * blockDim.x + threadIdx.x) >> 5;   // one warp per output
    int lane = threadIdx.x & 31;
    int b = gw >> 12;            // / 4096
    int j = gw & 4095;
    const float* t = t_emb + b * TT;
    const float* w = W + (size_t)j * TT;
    float acc = 0.f;
    #pragma unroll
    for (int i = lane * 4; i < TT; i += 128) {
        float4 tv = *(const float4*)(t + i);
        float4 wv = *(const float4*)(w + i);
        float sx = tv.x / (1.f + __expf(-tv.x));
        float sy = tv.y / (1.f + __expf(-tv.y));
        float sz = tv.z / (1.f + __expf(-tv.z));
        float sw = tv.w / (1.f + __expf(-tv.w));
        acc += sx * wv.x + sy * wv.y + sz * wv.z + sw * wv.w;
    }
    #pragma unroll
    for (int o = 16; o; o >>= 1) acc += __shfl_xor_sync(0xffffffffu, acc, o);
    if (lane == 0) g_emb[gw] = acc + bias[j];
}

// ------------------------- kernel 2: adaLN on ip_hidden_states -------------------------
__global__ void k_ipnorm(const float* __restrict__ ip) {
    __shared__ float red[64];
    int row = blockIdx.x;            // 0 .. B*LIP-1
    int b = row / LIP;
    const float* x = ip + (size_t)row * DD;
    int i0 = threadIdx.x * 8;        // 256 threads * 8 = 2048 = DD
    float4 v0 = *(const float4*)(x + i0);
    float4 v1 = *(const float4*)(x + i0 + 4);
    float s  = v0.x + v0.y + v0.z + v0.w + v1.x + v1.y + v1.z + v1.w;
    float ss = v0.x*v0.x + v0.y*v0.y + v0.z*v0.z + v0.w*v0.w
             + v1.x*v1.x + v1.y*v1.y + v1.z*v1.z + v1.w*v1.w;
    #pragma unroll
    for (int o = 16; o; o >>= 1) {
        s  += __shfl_xor_sync(0xffffffffu, s,  o);
        ss += __shfl_xor_sync(0xffffffffu, ss, o);
    }
    int w = threadIdx.x >> 5, lane = threadIdx.x & 31;
    if (lane == 0) { red[w] = s; red[32 + w] = ss; }
    __syncthreads();
    float fs = 0.f, fss = 0.f;
    #pragma unroll
    for (int k = 0; k < 8; k++) { fs += red[k]; fss += red[32 + k]; }
    float mu   = fs * (1.f / DD);
    float var  = fss * (1.f / DD) - mu * mu;
    float rstd = rsqrtf(var + 1e-6f);
    const float* shp = g_emb + b * TWOD;        // shift
    const float* scp = shp + DD;                // scale
    float* y = g_ipn + (size_t)row * DD;
    float4 sh0 = *(const float4*)(shp + i0), sh1 = *(const float4*)(shp + i0 + 4);
    float4 sc0 = *(const float4*)(scp + i0), sc1 = *(const float4*)(scp + i0 + 4);
    float4 o0, o1;
    o0.x = (v0.x - mu) * rstd * (1.f + sc0.x) + sh0.x;
    o0.y = (v0.y - mu) * rstd * (1.f + sc0.y) + sh0.y;
    o0.z = (v0.z - mu) * rstd * (1.f + sc0.z) + sh0.z;
    o0.w = (v0.w - mu) * rstd * (1.f + sc0.w) + sh0.w;
    o1.x = (v1.x - mu) * rstd * (1.f + sc1.x) + sh1.x;
    o1.y = (v1.y - mu) * rstd * (1.f + sc1.y) + sh1.y;
    o1.z = (v1.z - mu) * rstd * (1.f + sc1.z) + sh1.z;
    o1.w = (v1.w - mu) * rstd * (1.f + sc1.w) + sh1.w;
    *(float4*)(y + i0)     = o0;
    *(float4*)(y + i0 + 4) = o1;
}

// ------------------------- kernel 3: ip_key / ip_value GEMM -------------------------
// C[m][n] = sum_k A[m][k] * W[n][k]   (both K-major), M=1024, N=2048, K=2048
#define GK  16
#define GST 132
__global__ void k_gemm(const float* __restrict__ Wk, const float* __restrict__ Wv) {
    __shared__ float as[GK * GST];   // [k][m], padded
    __shared__ float bs[GK * GST];   // [k][n]
    const float* A  = g_ipn;
    const float* Bm = blockIdx.z ? Wv : Wk;
    float*       C  = blockIdx.z ? g_ipv : g_ipk;
    int m0 = blockIdx.y * 128, n0 = blockIdx.x * 128;
    int tid = threadIdx.x, tx = tid & 15, ty = tid >> 4;
    float c[8][8] = {};
    for (int k0 = 0; k0 < DD; k0 += GK) {
        #pragma unroll
        for (int it = 0; it < 2; it++) {
            int idx = tid + it * 256;          // 0..511
            int m = idx >> 2, kc = (idx & 3) * 4;
            float4 av = *(const float4*)(A  + (size_t)(m0 + m) * DD + k0 + kc);
            float4 bv = *(const float4*)(Bm + (size_t)(n0 + m) * DD + k0 + kc);
            as[(kc + 0) * GST + m] = av.x; as[(kc + 1) * GST + m] = av.y;
            as[(kc + 2) * GST + m] = av.z; as[(kc + 3) * GST + m] = av.w;
            bs[(kc + 0) * GST + m] = bv.x; bs[(kc + 1) * GST + m] = bv.y;
            bs[(kc + 2) * GST + m] = bv.z; bs[(kc + 3) * GST + m] = bv.w;
        }
        __syncthreads();
        #pragma unroll
        for (int kk = 0; kk < GK; kk++) {
            float a[8], bf[8];
            *(float4*)(a)      = *(const float4*)(as + kk * GST + ty * 8);
            *(float4*)(a + 4)  = *(const float4*)(as + kk * GST + ty * 8 + 4);
            *(float4*)(bf)     = *(const float4*)(bs + kk * GST + tx * 8);
            *(float4*)(bf + 4) = *(const float4*)(bs + kk * GST + tx * 8 + 4);
            #pragma unroll
            for (int i = 0; i < 8; i++)
                #pragma unroll
                for (int j = 0; j < 8; j++)
                    c[i][j] = fmaf(a[i], bf[j], c[i][j]);
        }
        __syncthreads();
    }
    #pragma unroll
    for (int i = 0; i < 8; i++) {
        float* cp = C + (size_t)(m0 + ty * 8 + i) * DD + n0 + tx * 8;
        *(float4*)(cp)     = make_float4(c[i][0], c[i][1], c[i][2], c[i][3]);
        *(float4*)(cp + 4) = make_float4(c[i][4], c[i][5], c[i][6], c[i][7]);
    }
}

// ------------------------- kernel 4: RMS-norm + head split/scatter -------------------------
__global__ void k_scatter(const float* __restrict__ q, const float* __restrict__ k,
                          const float* __restrict__ v,
                          const float* __restrict__ wq, const float* __restrict__ wk,
                          const float* __restrict__ wipk) {
    int gw   = (blockIdx.x * blockDim.x + threadIdx.x) >> 5;  // one warp per 128-elem row
    int lane = threadIdx.x & 31;
    const int NQ  = BB * HH * LL;    // 65536
    const int NIP = BB * HH * LIP;   // 16384
    const float* src; float* dst; const float* wptr = nullptr;
    float scale = 1.f; bool do_rms = false;

    int idx = gw;
    if (idx < NQ) {  // q
        int b = idx / (HH * LL), r = idx % (HH * LL), h = r / LL, l = r % LL;
        src = q + (size_t)(b * LL + l) * DD + h * DHD;
        dst = g_q + (size_t)idx * DHD;
        wptr = wq; do_rms = true; scale = 0.08838834764831845f;  // 1/sqrt(128)
    } else if ((idx -= NQ) < NQ) {  // k
        int b = idx / (HH * LL), r = idx % (HH * LL), h = r / LL, l = r % LL;
        src = k + (size_t)(b * LL + l) * DD + h * DHD;
        dst = g_k + ((size_t)(b * HH + h) * MM + l) * DHD;
        wptr = wk; do_rms = true;
    } else if ((idx -= NQ) < NIP) {  // kip
        int b = idx / (HH * LIP), r = idx % (HH * LIP), h = r / LIP, l = r % LIP;
        src = g_ipk + (size_t)(b * LIP + l) * DD + h * DHD;
        dst = g_k + ((size_t)(b * HH + h) * MM + LL + l) * DHD;
        wptr = wipk; do_rms = true;
    } else if ((idx -= NIP) < NQ) {  // v copy
        int b = idx / (HH * LL), r = idx % (HH * LL), h = r / LL, l = r % LL;
        src = v + (size_t)(b * LL + l) * DD + h * DHD;
        dst = g_v + ((size_t)(b * HH + h) * MM + l) * DHD;
    } else {  // vip copy
        idx -= NQ;
        int b = idx / (HH * LIP), r = idx % (HH * LIP), h = r / LIP, l = r % LIP;
        src = g_ipv + (size_t)(b * LIP + l) * DD + h * DHD;
        dst = g_v + ((size_t)(b * HH + h) * MM + LL + l) * DHD;
    }

    float4 val = *(const float4*)(src + lane * 4);
    if (do_rms) {
        float ss = val.x*val.x + val.y*val.y + val.z*val.z + val.w*val.w;
        #pragma unroll
        for (int o = 16; o; o >>= 1) ss += __shfl_xor_sync(0xffffffffu, ss, o);
        float r = rsqrtf(ss * (1.f / DHD) + 1e-6f) * scale;
        float4 w4 = *(const float4*)(wptr + lane * 4);
        val.x *= r * w4.x; val.y *= r * w4.y; val.z *= r * w4.z; val.w *= r * w4.w;
    }
    *(float4*)(dst + lane * 4) = val;
}

// ------------------------- kernel 5: flash attention (fp32) -------------------------
#define AQ  64
#define AK  64
#define QST 132
#define PST 68
__global__ void k_attn(float* __restrict__ out) {
    extern __shared__ float sm[];
    float* q_s = sm;                    // [64][132]
    float* k_s = q_s + AQ * QST;        // [64][132]
    float* v_s = k_s + AK * QST;        // [64][132]
    float* p_s = v_s + AK * QST;        // [64][68]
    int tid = threadIdx.x, tx = tid & 15, ty = tid >> 4;
    int b = blockIdx.z, h = blockIdx.y, qt = blockIdx.x;
    size_t bh = (size_t)b * HH + h;
    const float* Q = g_q + (bh * LL + (size_t)qt * AQ) * DHD;
    const float* K = g_k + bh * MM * DHD;
    const float* V = g_v + bh * MM * DHD;

    #pragma unroll
    for (int it = 0; it < 8; it++) {
        int idx = tid + it * 256;          // 0..2047
        int r = idx >> 5, c = (idx & 31) * 4;
        *(float4*)(q_s + r * QST + c) = *(const float4*)(Q + r * DHD + c);
    }
    float m[4], lsum[4] = {0.f, 0.f, 0.f, 0.f};
    float o[4][8] = {};
    #pragma unroll
    for (int i = 0; i < 4; i++) m[i] = -1e30f;
    __syncthreads();

    for (int kt = 0; kt < MM; kt += AK) {
        #pragma unroll
        for (int it = 0; it < 8; it++) {
            int idx = tid + it * 256;
            int r = idx >> 5, c = (idx & 31) * 4;
            *(float4*)(k_s + r * QST + c) = *(const float4*)(K + (size_t)(kt + r) * DHD + c);
            *(float4*)(v_s + r * QST + c) = *(const float4*)(V + (size_t)(kt + r) * DHD + c);
        }
        __syncthreads();

        // S = Q @ K^T  (rows: ty+16i, cols: tx+16j)
        float s[4][4] = {};
        #pragma unroll 2
        for (int kk = 0; kk < DHD; kk += 4) {
            float4 a[4], bf[4];
            #pragma unroll
            for (int i = 0; i < 4; i++) a[i]  = *(const float4*)(q_s + (ty + 16 * i) * QST + kk);
            #pragma unroll
            for (int j = 0; j < 4; j++) bf[j] = *(const float4*)(k_s + (tx + 16 * j) * QST + kk);
            #pragma unroll
            for (int i = 0; i < 4; i++)
                #pragma unroll
                for (int j = 0; j < 4; j++) {
                    s[i][j] = fmaf(a[i].x, bf[j].x, s[i][j]);
                    s[i][j] = fmaf(a[i].y, bf[j].y, s[i][j]);
                    s[i][j] = fmaf(a[i].z, bf[j].z, s[i][j]);
                    s[i][j] = fmaf(a[i].w, bf[j].w, s[i][j]);
                }
        }

        // online softmax (row reduce across tx: lanes differ in low 4 bits of lane id)
        #pragma unroll
        for (int i = 0; i < 4; i++) {
            float mx = fmaxf(fmaxf(s[i][0], s[i][1]), fmaxf(s[i][2], s[i][3]));
            #pragma unroll
            for (int ofs = 8; ofs; ofs >>= 1) mx = fmaxf(mx, __shfl_xor_sync(0xffffffffu, mx, ofs));
            float mn = fmaxf(m[i], mx);
            float alpha = __expf(m[i] - mn);
            m[i] = mn;
            float rs = 0.f;
            #pragma unroll
            for (int j = 0; j < 4; j++) { s[i][j] = __expf(s[i][j] - mn); rs += s[i][j]; }
            lsum[i] = lsum[i] * alpha + rs;
            #pragma unroll
            for (int c = 0; c < 8; c++) o[i][c] *= alpha;
        }
        #pragma unroll
        for (int i = 0; i < 4; i++)
            #pragma unroll
            for (int j = 0; j < 4; j++)
                p_s[(ty + 16 * i) * PST + tx + 16 * j] = s[i][j];
        __syncthreads();

        // O += P @ V   (O cols: tx*8 .. tx*8+7)
        #pragma unroll 2
        for (int kp = 0; kp < AK; kp++) {
            float p[4];
            #pragma unroll
            for (int i = 0; i < 4; i++) p[i] = p_s[(ty + 16 * i) * PST + kp];
            float4 v0 = *(const float4*)(v_s + kp * QST + tx * 8);
            float4 v1 = *(const float4*)(v_s + kp * QST + tx * 8 + 4);
            #pragma unroll
            for (int i = 0; i < 4; i++) {
                o[i][0] = fmaf(p[i], v0.x, o[i][0]);
                o[i][1] = fmaf(p[i], v0.y, o[i][1]);
                o[i][2] = fmaf(p[i], v0.z, o[i][2]);
                o[i][3] = fmaf(p[i], v0.w, o[i][3]);
                o[i][4] = fmaf(p[i], v1.x, o[i][4]);
                o[i][5] = fmaf(p[i], v1.y, o[i][5]);
                o[i][6] = fmaf(p[i], v1.z, o[i][6]);
                o[i][7] = fmaf(p[i], v1.w, o[i][7]);
            }
        }
        __syncthreads();
    }

    #pragma unroll
    for (int i = 0; i < 4; i++) {
        float ls = lsum[i];
        #pragma unroll
        for (int ofs = 8; ofs; ofs >>= 1) ls += __shfl_xor_sync(0xffffffffu, ls, ofs);
        float inv = 1.f / ls;
        int l = qt * AQ + ty + 16 * i;
        float* op = out + (size_t)(b * LL + l) * DD + h * DHD + tx * 8;
        *(float4*)(op)     = make_float4(o[i][0]*inv, o[i][1]*inv, o[i][2]*inv, o[i][3]*inv);
        *(float4*)(op + 4) = make_float4(o[i][4]*inv, o[i][5]*inv, o[i][6]*inv, o[i][7]*inv);
    }
}

// ------------------------- launch -------------------------
extern "C" void kernel_launch(void* const* d_in, const int* in_sizes, int n_in,
                              void* d_out, int out_size) {
    const float* ip   = (const float*)d_in[0];
    const float* q    = (const float*)d_in[1];
    const float* k    = (const float*)d_in[2];
    const float* v    = (const float*)d_in[3];
    const float* temb = (const float*)d_in[4];
    const float* Wada = (const float*)d_in[5];
    const float* bada = (const float*)d_in[6];
    const float* Wk   = (const float*)d_in[7];
    const float* Wv   = (const float*)d_in[8];
    const float* wq   = (const float*)d_in[9];
    const float* wk   = (const float*)d_in[10];
    const float* wipk = (const float*)d_in[11];
    float* out = (float*)d_out;

    k_emb<<<(BB * TWOD) / 8, 256>>>(temb, Wada, bada);
    k_ipnorm<<<BB * LIP, 256>>>(ip);
    dim3 gg(DD / 128, (BB * LIP) / 128, 2);
    k_gemm<<<gg, 256>>>(Wk, Wv);
    int totw = BB * HH * (LL * 3 + LIP * 2);     // 229376 warps
    k_scatter<<<totw / 8, 256>>>(q, k, v, wq, wk, wipk);

    int smem = (3 * AQ * QST + AK * PST) * sizeof(float);   // 118784 B
    cudaFuncSetAttribute(k_attn, cudaFuncAttributeMaxDynamicSharedMemorySize, smem);
    dim3 ga(LL / AQ, HH, BB);
    k_attn<<<ga, 256, smem>>>(out);
}